// round 14
// baseline (speedup 1.0000x reference)
#include <cuda_runtime.h>
#include <cuda_fp16.h>
#include <cstdint>

// ---------------- static scratch (no allocations allowed) ----------------
#define NMAX 122880
#define EMAX 983040

__device__ float g_dinv[NMAX];
__device__ int   g_deg[NMAX];
__device__ int   g_rowptr[NMAX + 1];
__device__ int   g_cursor[NMAX];
__device__ int   g_csr[EMAX];
__device__ int   g_bsum[256];
__device__ int   g_bsumx[256];
__device__ int   g_is64;

__device__ __half g_xh[NMAX * 64];
__device__ __half g_agg1[NMAX * 64];
__device__ __half g_y1[NMAX * 128];
__device__ __half g_g2[NMAX * 64];
__device__ __half g_bufH[NMAX * 64];            // FC A operand [4096][1920]
__device__ __half g_W1h[32 * 128 * 2];
__device__ __half g_W2h[64 * 64 * 2];
// Wfc^T for FC: [27 nblk][30 kchunk][64 n][32 kp] half2 linear
__device__ __half g_Wt[14 * 30 * 8192];         // (reuse; 27*30*4096 = 3.32M <= 3.44M)

// ---------------- zero degrees + dtype detection (merged) ----------------
__global__ void k_zero_detect(const int* __restrict__ w, int n) {
    int i = blockIdx.x * blockDim.x + threadIdx.x;
    if (i < n) g_deg[i] = 0;
    if (i == 0) g_is64 = 1;
    if (i < 4096 && (i & 1) && w[i] != 0) g_is64 = 0;
}

__device__ __forceinline__ int load_idx(const int* w, long long pos) {
    return g_is64 ? w[2 * pos] : w[(int)pos];
}

__global__ void k_count(const int* __restrict__ w, int E, int n) {
    int e = blockIdx.x * blockDim.x + threadIdx.x;
    if (e < E) {
        int d = load_idx(w, (long long)E + e);
        d = min(max(d, 0), n - 1);
        atomicAdd(&g_deg[d], 1);
    }
}

// ---------------- exclusive scan (scan1 also computes dinv) ----------------
__global__ void k_scan1(int n) {
    __shared__ int sh[1024];
    int gid = blockIdx.x * 1024 + threadIdx.x;
    int v = (gid < n) ? g_deg[gid] : 0;
    sh[threadIdx.x] = v;
    __syncthreads();
    for (int off = 1; off < 1024; off <<= 1) {
        int t = (threadIdx.x >= off) ? sh[threadIdx.x - off] : 0;
        __syncthreads();
        sh[threadIdx.x] += t;
        __syncthreads();
    }
    if (gid < n) {
        g_rowptr[gid] = sh[threadIdx.x] - v;
        g_dinv[gid] = rsqrtf((float)(v + 1));
    }
    if (threadIdx.x == 1023) g_bsum[blockIdx.x] = sh[1023];
}

__global__ void k_scan2(int nb) {
    __shared__ int sh[1024];
    int v = (threadIdx.x < nb) ? g_bsum[threadIdx.x] : 0;
    sh[threadIdx.x] = v;
    __syncthreads();
    for (int off = 1; off < 1024; off <<= 1) {
        int t = (threadIdx.x >= off) ? sh[threadIdx.x - off] : 0;
        __syncthreads();
        sh[threadIdx.x] += t;
        __syncthreads();
    }
    if (threadIdx.x < nb) g_bsumx[threadIdx.x] = sh[threadIdx.x] - v;
}

__global__ void k_scan3(int n, int E) {
    int gid = blockIdx.x * 1024 + threadIdx.x;
    if (gid < n) {
        int r = g_rowptr[gid] + g_bsumx[blockIdx.x];
        g_rowptr[gid] = r;
        g_cursor[gid] = r;
    }
    if (gid == 0) g_rowptr[n] = E;
}

__global__ void k_fill(const int* __restrict__ w, int E, int n) {
    int e = blockIdx.x * blockDim.x + threadIdx.x;
    if (e < E) {
        int d = load_idx(w, (long long)E + e);
        int s = load_idx(w, e);
        d = min(max(d, 0), n - 1);
        s = min(max(s, 0), n - 1);
        int slot = atomicAdd(&g_cursor[d], 1);
        g_csr[min(slot, EMAX - 1)] = s;
    }
}

// ---------------- all weight conversions in one kernel ----------------
__global__ void k_cvt_all(const float* __restrict__ W1, const float* __restrict__ W2,
                          const float* __restrict__ Wfc, int N) {
    int idx = blockIdx.x * blockDim.x + threadIdx.x;
    if (idx < 4096) {
        int n = idx & 127, kp = idx >> 7;
        ((__half2*)g_W1h)[idx] =
            __floats2half2_rn(W1[(2 * kp) * 128 + n], W1[(2 * kp + 1) * 128 + n]);
    } else if (idx < 8192) {
        int j = idx - 4096;
        int n = j & 63, kp = j >> 6;
        ((__half2*)g_W2h)[j] =
            __floats2half2_rn(W2[(2 * kp) * 64 + n], W2[(2 * kp + 1) * 64 + n]);
    } else {
        int j = idx - 8192;
        if (j < 27 * 30 * 2048) {
            int kp = j & 31;
            int n  = (j >> 5) & 63;
            int c  = (j >> 11) % 30;
            int nb = j / 61440;            // 30*2048
            int gn = nb * 64 + n;
            int gk = c * 64 + 2 * kp;
            float lo = 0.f, hi = 0.f;
            if (gn < N) {
                lo = Wfc[(long long)gk * N + gn];
                hi = Wfc[(long long)(gk + 1) * N + gn];
            }
            ((__half2*)g_Wt)[j] = __floats2half2_rn(lo, hi);
        }
    }
}

// ---------------- xh = half(dinv * x) ----------------
__global__ void k_scale_x(const float* __restrict__ x, int n) {
    int idx = blockIdx.x * blockDim.x + threadIdx.x;
    if (idx >= n * 32) return;
    int node = idx >> 5;
    float2 v = ((const float2*)x)[idx];
    float di = g_dinv[node];
    ((__half2*)g_xh)[idx] = __floats2half2_rn(v.x * di, v.y * di);
}

// ---------------- gathers (edge loop unrolled x4) ----------------
__global__ void k_gather_in(int n) {
    int w = (blockIdx.x * blockDim.x + threadIdx.x) >> 5;
    int lane = threadIdx.x & 31;
    if (w >= n) return;
    const __half2* src = (const __half2*)g_xh;
    float2 acc = __half22float2(src[w * 32 + lane]);
    int e0 = g_rowptr[w], e1 = g_rowptr[w + 1];
    int e = e0;
    for (; e + 4 <= e1; e += 4) {
        int s0 = g_csr[e], s1 = g_csr[e + 1], s2 = g_csr[e + 2], s3 = g_csr[e + 3];
        float2 v0 = __half22float2(src[s0 * 32 + lane]);
        float2 v1 = __half22float2(src[s1 * 32 + lane]);
        float2 v2 = __half22float2(src[s2 * 32 + lane]);
        float2 v3 = __half22float2(src[s3 * 32 + lane]);
        acc.x += (v0.x + v1.x) + (v2.x + v3.x);
        acc.y += (v0.y + v1.y) + (v2.y + v3.y);
    }
    for (; e < e1; e++) {
        float2 v = __half22float2(src[g_csr[e] * 32 + lane]);
        acc.x += v.x; acc.y += v.y;
    }
    ((__half2*)g_agg1)[w * 32 + lane] = __floats2half2_rn(acc.x, acc.y);
}

__global__ void k_gather_out(const float* __restrict__ b2, int n) {
    int w = (blockIdx.x * blockDim.x + threadIdx.x) >> 5;
    int lane = threadIdx.x & 31;
    if (w >= n) return;
    const __half2* src = (const __half2*)g_g2;
    float2 acc = __half22float2(src[w * 32 + lane]);
    int e0 = g_rowptr[w], e1 = g_rowptr[w + 1];
    int e = e0;
    for (; e + 4 <= e1; e += 4) {
        int s0 = g_csr[e], s1 = g_csr[e + 1], s2 = g_csr[e + 2], s3 = g_csr[e + 3];
        float2 v0 = __half22float2(src[s0 * 32 + lane]);
        float2 v1 = __half22float2(src[s1 * 32 + lane]);
        float2 v2 = __half22float2(src[s2 * 32 + lane]);
        float2 v3 = __half22float2(src[s3 * 32 + lane]);
        acc.x += (v0.x + v1.x) + (v2.x + v3.x);
        acc.y += (v0.y + v1.y) + (v2.y + v3.y);
    }
    for (; e < e1; e++) {
        float2 v = __half22float2(src[g_csr[e] * 32 + lane]);
        acc.x += v.x; acc.y += v.y;
    }
    float di = g_dinv[w];
    float2 bb = *(const float2*)&b2[lane * 2];
    float ox = fmaxf(di * acc.x + bb.x, 0.f);
    float oy = fmaxf(di * acc.y + bb.y, 0.f);
    ((__half2*)g_bufH)[w * 32 + lane] = __floats2half2_rn(ox, oy);
}

// ---------------- GEMM1 fp16 (mma.sync) ----------------
#define G1_LDA 36

__global__ __launch_bounds__(256) void k_gemm1h(const float* __restrict__ b1, int n) {
    __shared__ unsigned As[128 * G1_LDA];
    __shared__ unsigned Bs[32 * 128];
    int tid = threadIdx.x;
    int r0 = blockIdx.x * 128;

    int w = tid >> 5, lane = tid & 31;
    int wm = (w >> 1) * 32, wn = (w & 1) * 64;
    int g = lane >> 2, t = lane & 3;

#pragma unroll
    for (int k = 0; k < 4; k++) {
        int ut = tid + k * 256;
        int row = ut >> 3, q = ut & 7;
        uint4 v = ((const uint4*)(g_agg1 + (long long)(r0 + row) * 64))[q];
        *(uint4*)&As[row * G1_LDA + q * 4] = v;
    }
#pragma unroll
    for (int k = 0; k < 4; k++) {
        int ut = tid + k * 256;
        int kp = ut >> 5, nc = (ut & 31) * 4;
        uint4 v = ((const uint4*)g_W1h)[ut];
        *(uint4*)&Bs[kp * 128 + (nc ^ ((kp & 3) << 3))] = v;
    }
    __syncthreads();

    float c[2][8][4];
#pragma unroll
    for (int i = 0; i < 2; i++)
#pragma unroll
        for (int j = 0; j < 8; j++)
#pragma unroll
            for (int q = 0; q < 4; q++) c[i][j][q] = 0.f;

#pragma unroll
    for (int ks = 0; ks < 4; ks++) {
        unsigned af[2][4];
#pragma unroll
        for (int i = 0; i < 2; i++) {
            int row = wm + 16 * i + g;
            int kp0 = 8 * ks + t;
            af[i][0] = As[row * G1_LDA + kp0];
            af[i][1] = As[(row + 8) * G1_LDA + kp0];
            af[i][2] = As[row * G1_LDA + kp0 + 4];
            af[i][3] = As[(row + 8) * G1_LDA + kp0 + 4];
        }
        unsigned bf[8][2];
#pragma unroll
        for (int j = 0; j < 8; j++) {
            int nn = (wn + 8 * j + g) ^ (t << 3);
            bf[j][0] = Bs[(8 * ks + t) * 128 + nn];
            bf[j][1] = Bs[(8 * ks + 4 + t) * 128 + nn];
        }
#pragma unroll
        for (int i = 0; i < 2; i++)
#pragma unroll
            for (int j = 0; j < 8; j++) {
                asm volatile(
                    "mma.sync.aligned.m16n8k16.row.col.f32.f16.f16.f32 "
                    "{%0,%1,%2,%3}, {%4,%5,%6,%7}, {%8,%9}, {%0,%1,%2,%3};"
                    : "+f"(c[i][j][0]), "+f"(c[i][j][1]),
                      "+f"(c[i][j][2]), "+f"(c[i][j][3])
                    : "r"(af[i][0]), "r"(af[i][1]), "r"(af[i][2]), "r"(af[i][3]),
                      "r"(bf[j][0]), "r"(bf[j][1]));
            }
    }

#pragma unroll
    for (int i = 0; i < 2; i++) {
        int row = wm + 16 * i + g;
#pragma unroll
        for (int j = 0; j < 8; j++) {
            int col = wn + 8 * j + 2 * t;
            float2 bb = *(const float2*)&b1[col];
            int node0 = r0 + row;
            int node1 = node0 + 8;
            float d0 = g_dinv[node0], d1 = g_dinv[node1];
            ((__half2*)g_y1)[(long long)node0 * 64 + col / 2] =
                __floats2half2_rn(fmaxf(d0 * c[i][j][0] + bb.x, 0.f),
                                  fmaxf(d0 * c[i][j][1] + bb.y, 0.f));
            ((__half2*)g_y1)[(long long)node1 * 64 + col / 2] =
                __floats2half2_rn(fmaxf(d1 * c[i][j][2] + bb.x, 0.f),
                                  fmaxf(d1 * c[i][j][3] + bb.y, 0.f));
        }
    }
}

// ---------------- GEMM2 fp16 (mma.sync) ----------------
#define G2_LDA 68

__global__ __launch_bounds__(256) void k_gemm2h(int n) {
    __shared__ unsigned As[64 * G2_LDA];
    __shared__ unsigned Bs[64 * 64];
    int tid = threadIdx.x;
    int r0 = blockIdx.x * 64;

    int w = tid >> 5, lane = tid & 31;
    int wm = (w >> 1) * 16, wn = (w & 1) * 32;
    int g = lane >> 2, t = lane & 3;

#pragma unroll
    for (int k = 0; k < 4; k++) {
        int ut = tid + k * 256;
        int row = ut >> 4, q = ut & 15;
        uint4 v = ((const uint4*)(g_y1 + (long long)(r0 + row) * 128))[q];
        *(uint4*)&As[row * G2_LDA + q * 4] = v;
    }
#pragma unroll
    for (int k = 0; k < 4; k++) {
        int ut = tid + k * 256;
        int kp = ut >> 4, nc = (ut & 15) * 4;
        uint4 v = ((const uint4*)g_W2h)[ut];
        *(uint4*)&Bs[kp * 64 + (nc ^ ((kp & 3) << 3))] = v;
    }
    __syncthreads();

    float c[4][4];
#pragma unroll
    for (int j = 0; j < 4; j++)
#pragma unroll
        for (int q = 0; q < 4; q++) c[j][q] = 0.f;

#pragma unroll
    for (int ks = 0; ks < 8; ks++) {
        unsigned af[4];
        {
            int row = wm + g;
            int kp0 = 8 * ks + t;
            af[0] = As[row * G2_LDA + kp0];
            af[1] = As[(row + 8) * G2_LDA + kp0];
            af[2] = As[row * G2_LDA + kp0 + 4];
            af[3] = As[(row + 8) * G2_LDA + kp0 + 4];
        }
        unsigned bf[4][2];
#pragma unroll
        for (int j = 0; j < 4; j++) {
            int nn = (wn + 8 * j + g) ^ (t << 3);
            bf[j][0] = Bs[(8 * ks + t) * 64 + nn];
            bf[j][1] = Bs[(8 * ks + 4 + t) * 64 + nn];
        }
#pragma unroll
        for (int j = 0; j < 4; j++) {
            asm volatile(
                "mma.sync.aligned.m16n8k16.row.col.f32.f16.f16.f32 "
                "{%0,%1,%2,%3}, {%4,%5,%6,%7}, {%8,%9}, {%0,%1,%2,%3};"
                : "+f"(c[j][0]), "+f"(c[j][1]), "+f"(c[j][2]), "+f"(c[j][3])
                : "r"(af[0]), "r"(af[1]), "r"(af[2]), "r"(af[3]),
                  "r"(bf[j][0]), "r"(bf[j][1]));
        }
    }

    {
        int row = wm + g;
        int node0 = r0 + row, node1 = node0 + 8;
        float d0 = g_dinv[node0], d1 = g_dinv[node1];
#pragma unroll
        for (int j = 0; j < 4; j++) {
            int col = wn + 8 * j + 2 * t;
            ((__half2*)g_g2)[(long long)node0 * 32 + col / 2] =
                __floats2half2_rn(d0 * c[j][0], d0 * c[j][1]);
            ((__half2*)g_g2)[(long long)node1 * 32 + col / 2] =
                __floats2half2_rn(d1 * c[j][2], d1 * c[j][3]);
        }
    }
}

// ---------------- FC fp16 mma.sync (fp32 acc), cp.async pipeline, 2 CTAs/SM ----
// Block tile 128m x 64n, 256 thr / 8 warps (4m x 2n of 32x32), BK=64,
// double buffered via cp.async. N=1728=27*64 exactly. 864 CTAs.
#define FC_STG 27648
#define FC_SMEM (1024 + 2 * FC_STG)

__device__ __forceinline__ uint32_t smem_u32(const void* p) {
    uint32_t a;
    asm("{ .reg .u64 t; cvta.to.shared.u64 t, %1; cvt.u32.u64 %0, t; }" : "=r"(a) : "l"(p));
    return a;
}

__device__ __forceinline__ void cpa16(uint32_t dst, const void* src) {
    asm volatile("cp.async.cg.shared.global [%0], [%1], 16;"
                 :: "r"(dst), "l"(src) : "memory");
}

__global__ __launch_bounds__(256, 2) void k_fc2(const float* __restrict__ bias,
                                                float* __restrict__ out,
                                                int M, int N, int K,
                                                int nchunks) {
    extern __shared__ char sm[];
    uint32_t sb = smem_u32(sm);
    int tid = threadIdx.x, wid = tid >> 5, lane = tid & 31;
    int wm = (wid & 3) * 32, wn = (wid >> 2) * 32;
    int g = lane >> 2, t = lane & 3;
    int lrow = lane & 15, lcolw = (lane >> 4) * 4;
    const __half* A = g_bufH;

    int nb = blockIdx.x % 27;
    int m0 = (blockIdx.x / 27) * 128;
    int n0 = nb * 64;
    const __half2* Bt = (const __half2*)g_Wt + (long long)(nb * 30) * 2048;

    if (tid < 64) *(float*)(sm + 512 + tid * 4) = bias[n0 + tid];

    float c[2][4][4];
#pragma unroll
    for (int i = 0; i < 2; i++)
#pragma unroll
        for (int j = 0; j < 4; j++)
#pragma unroll
            for (int q = 0; q < 4; q++) c[i][j][q] = 0.f;

    // per-thread copy coords (fixed across chunks)
    int a_r[4], a_q[4];
#pragma unroll
    for (int i = 0; i < 4; i++) { int ut = tid + i * 256; a_r[i] = ut >> 3; a_q[i] = ut & 7; }
    int b_r[2], b_q[2];
#pragma unroll
    for (int i = 0; i < 2; i++) { int ut = tid + i * 256; b_r[i] = ut >> 3; b_q[i] = ut & 7; }

    // prologue: chunk 0 -> stage 0 via cp.async
    {
        uint32_t sA = sb + 1024, sB = sA + 18432;
#pragma unroll
        for (int i = 0; i < 4; i++)
            cpa16(sA + (uint32_t)((a_r[i] * 36 + a_q[i] * 4) * 4),
                  A + (long long)(m0 + a_r[i]) * K + a_q[i] * 8);
#pragma unroll
        for (int i = 0; i < 2; i++)
            cpa16(sB + (uint32_t)((b_r[i] * 36 + b_q[i] * 4) * 4),
                  Bt + (long long)b_r[i] * 32 + b_q[i] * 4);
        asm volatile("cp.async.commit_group;" ::: "memory");
        asm volatile("cp.async.wait_group 0;" ::: "memory");
    }
    __syncthreads();

    for (int ch = 0; ch < nchunks; ch++) {
        int cur = ch & 1;
        bool hn = (ch + 1) < nchunks;
        if (hn) {
            // prefetch chunk ch+1 into the other stage
            uint32_t dA = sb + 1024 + ((ch + 1) & 1) * FC_STG;
            uint32_t dB = dA + 18432;
            int kc = (ch + 1) * 64;
            const __half2* Bc = Bt + (long long)(ch + 1) * 2048;
#pragma unroll
            for (int i = 0; i < 4; i++)
                cpa16(dA + (uint32_t)((a_r[i] * 36 + a_q[i] * 4) * 4),
                      A + (long long)(m0 + a_r[i]) * K + kc + a_q[i] * 8);
#pragma unroll
            for (int i = 0; i < 2; i++)
                cpa16(dB + (uint32_t)((b_r[i] * 36 + b_q[i] * 4) * 4),
                      Bc + (long long)b_r[i] * 32 + b_q[i] * 4);
            asm volatile("cp.async.commit_group;" ::: "memory");
        }

        uint32_t sA = sb + 1024 + cur * FC_STG;
        uint32_t sB = sA + 18432;
#pragma unroll
        for (int ks = 0; ks < 4; ks++) {
            int kw = ks * 8 + lcolw;
            unsigned af[2][4], bf[4][2];
#pragma unroll
            for (int i = 0; i < 2; i++) {
                uint32_t ad = sA + (uint32_t)(((wm + 16 * i + lrow) * 36 + kw) * 4);
                asm volatile(
                    "ldmatrix.sync.aligned.m8n8.x4.shared.b16 {%0,%1,%2,%3}, [%4];"
                    : "=r"(af[i][0]), "=r"(af[i][1]), "=r"(af[i][2]), "=r"(af[i][3])
                    : "r"(ad));
            }
#pragma unroll
            for (int jb = 0; jb < 2; jb++) {
                unsigned q0, q1, q2, q3;
                uint32_t bd = sB + (uint32_t)(((wn + 16 * jb + lrow) * 36 + kw) * 4);
                asm volatile(
                    "ldmatrix.sync.aligned.m8n8.x4.shared.b16 {%0,%1,%2,%3}, [%4];"
                    : "=r"(q0), "=r"(q1), "=r"(q2), "=r"(q3)
                    : "r"(bd));
                bf[2 * jb][0] = q0; bf[2 * jb + 1][0] = q1;
                bf[2 * jb][1] = q2; bf[2 * jb + 1][1] = q3;
            }
#pragma unroll
            for (int i = 0; i < 2; i++)
#pragma unroll
                for (int j = 0; j < 4; j++) {
                    asm volatile(
                        "mma.sync.aligned.m16n8k16.row.col.f32.f16.f16.f32 "
                        "{%0,%1,%2,%3}, {%4,%5,%6,%7}, {%8,%9}, {%0,%1,%2,%3};"
                        : "+f"(c[i][j][0]), "+f"(c[i][j][1]),
                          "+f"(c[i][j][2]), "+f"(c[i][j][3])
                        : "r"(af[i][0]), "r"(af[i][1]), "r"(af[i][2]), "r"(af[i][3]),
                          "r"(bf[j][0]), "r"(bf[j][1]));
                }
        }

        if (hn) asm volatile("cp.async.wait_group 0;" ::: "memory");
        __syncthreads();
    }

    // epilogue
    const float* bs = (const float*)(sm + 512);
#pragma unroll
    for (int i = 0; i < 2; i++) {
        int row = m0 + wm + 16 * i + g;
#pragma unroll
        for (int j = 0; j < 4; j++) {
            int lb = wn + 8 * j + 2 * t;
            int cb = n0 + lb;
            float2 bb = make_float2(bs[lb], bs[lb + 1]);
            float2 o0 = make_float2(c[i][j][0] + bb.x, c[i][j][1] + bb.y);
            float2 o1 = make_float2(c[i][j][2] + bb.x, c[i][j][3] + bb.y);
            *(float2*)&out[(long long)row * N + cb] = o0;
            *(float2*)&out[(long long)(row + 8) * N + cb] = o1;
        }
    }
}

// ---------------- launch ----------------
extern "C" void kernel_launch(void* const* d_in, const int* in_sizes, int n_in,
                              void* d_out, int out_size) {
    const float* x   = (const float*)d_in[0];
    const int*   ei  = (const int*)d_in[1];
    const float* W1  = (const float*)d_in[2];
    const float* b1  = (const float*)d_in[3];
    const float* W2  = (const float*)d_in[4];
    const float* b2  = (const float*)d_in[5];
    const float* Wfc = (const float*)d_in[6];
    const float* bfc = (const float*)d_in[7];
    float* out = (float*)d_out;

    int n = in_sizes[0] / 64;     // 122880
    int E = in_sizes[1] / 2;      // 983040
    int M = out_size / 1728;      // 4096
    int Nfc = 1728, Kfc = 1920;
    int ntiles = 27 * (M / 128);  // 864

    static int fc_attr_set = 0;
    if (!fc_attr_set) {
        cudaFuncSetAttribute(k_fc2, cudaFuncAttributeMaxDynamicSharedMemorySize, FC_SMEM);
        fc_attr_set = 1;
    }

    // graph structure
    k_zero_detect<<<(n + 255) / 256, 256>>>(ei, n);
    k_count<<<(E + 255) / 256, 256>>>(ei, E, n);
    int nb = (n + 1023) / 1024;
    k_scan1<<<nb, 1024>>>(n);
    k_scan2<<<1, 1024>>>(nb);
    k_scan3<<<nb, 1024>>>(n, E);
    k_fill<<<(E + 255) / 256, 256>>>(ei, E, n);

    // weights (single kernel)
    int cvt_tot = 8192 + 27 * 30 * 2048;
    k_cvt_all<<<(cvt_tot + 255) / 256, 256>>>(W1, W2, Wfc, Nfc);

    // node pipeline
    k_scale_x<<<(n * 32 + 255) / 256, 256>>>(x, n);
    k_gather_in<<<(n * 32 + 255) / 256, 256>>>(n);
    k_gemm1h<<<n / 128, 256>>>(b1, n);
    k_gemm2h<<<n / 64, 256>>>(n);
    k_gather_out<<<(n * 32 + 255) / 256, 256>>>(b2, n);

    // FC head: 864 CTAs, 2 per SM
    k_fc2<<<ntiles, 256, FC_SMEM>>>(bfc, out, M, Nfc, Kfc, 30);
}

// round 15
// speedup vs baseline: 1.0496x; 1.0496x over previous
#include <cuda_runtime.h>
#include <cuda_fp16.h>
#include <cstdint>

// ---------------- static scratch (no allocations allowed) ----------------
#define NMAX 122880
#define EMAX 983040

__device__ float g_dinv[NMAX];
__device__ int   g_deg[NMAX];
__device__ int   g_rowptr[NMAX + 1];
__device__ int   g_cursor[NMAX];
__device__ int   g_csr[EMAX];
__device__ int   g_bsum[256];
__device__ int   g_bsumx[256];
__device__ int   g_is64;

__device__ __half g_xh[NMAX * 64];
__device__ __half g_agg1[NMAX * 64];
__device__ __half g_y1[NMAX * 128];
__device__ __half g_g2[NMAX * 64];
__device__ __half g_bufH[NMAX * 64];            // FC A operand [4096][1920]
__device__ __half g_W1h[32 * 128 * 2];
__device__ __half g_W2h[64 * 64 * 2];
// Wfc^T for FC: [27 nblk][30 kchunk][64 n][32 kp] half2 linear
__device__ __half g_Wt[14 * 30 * 8192];         // (reuse; 27*30*4096 = 3.32M <= 3.44M)

// ---------------- zero degrees + dtype detection (merged) ----------------
__global__ void k_zero_detect(const int* __restrict__ w, int n) {
    int i = blockIdx.x * blockDim.x + threadIdx.x;
    if (i < n) g_deg[i] = 0;
    if (i == 0) g_is64 = 1;
    if (i < 4096 && (i & 1) && w[i] != 0) g_is64 = 0;
}

__device__ __forceinline__ int load_idx(const int* w, long long pos) {
    return g_is64 ? w[2 * pos] : w[(int)pos];
}

__global__ void k_count(const int* __restrict__ w, int E, int n) {
    int e = blockIdx.x * blockDim.x + threadIdx.x;
    if (e < E) {
        int d = load_idx(w, (long long)E + e);
        d = min(max(d, 0), n - 1);
        atomicAdd(&g_deg[d], 1);
    }
}

// ---------------- exclusive scan (scan1 also computes dinv) ----------------
__global__ void k_scan1(int n) {
    __shared__ int sh[1024];
    int gid = blockIdx.x * 1024 + threadIdx.x;
    int v = (gid < n) ? g_deg[gid] : 0;
    sh[threadIdx.x] = v;
    __syncthreads();
    for (int off = 1; off < 1024; off <<= 1) {
        int t = (threadIdx.x >= off) ? sh[threadIdx.x - off] : 0;
        __syncthreads();
        sh[threadIdx.x] += t;
        __syncthreads();
    }
    if (gid < n) {
        g_rowptr[gid] = sh[threadIdx.x] - v;
        g_dinv[gid] = rsqrtf((float)(v + 1));
    }
    if (threadIdx.x == 1023) g_bsum[blockIdx.x] = sh[1023];
}

__global__ void k_scan2(int nb) {
    __shared__ int sh[1024];
    int v = (threadIdx.x < nb) ? g_bsum[threadIdx.x] : 0;
    sh[threadIdx.x] = v;
    __syncthreads();
    for (int off = 1; off < 1024; off <<= 1) {
        int t = (threadIdx.x >= off) ? sh[threadIdx.x - off] : 0;
        __syncthreads();
        sh[threadIdx.x] += t;
        __syncthreads();
    }
    if (threadIdx.x < nb) g_bsumx[threadIdx.x] = sh[threadIdx.x] - v;
}

__global__ void k_scan3(int n, int E) {
    int gid = blockIdx.x * 1024 + threadIdx.x;
    if (gid < n) {
        int r = g_rowptr[gid] + g_bsumx[blockIdx.x];
        g_rowptr[gid] = r;
        g_cursor[gid] = r;
    }
    if (gid == 0) g_rowptr[n] = E;
}

__global__ void k_fill(const int* __restrict__ w, int E, int n) {
    int e = blockIdx.x * blockDim.x + threadIdx.x;
    if (e < E) {
        int d = load_idx(w, (long long)E + e);
        int s = load_idx(w, e);
        d = min(max(d, 0), n - 1);
        s = min(max(s, 0), n - 1);
        int slot = atomicAdd(&g_cursor[d], 1);
        g_csr[min(slot, EMAX - 1)] = s;
    }
}

// ---------------- all weight conversions in one kernel ----------------
__global__ void k_cvt_all(const float* __restrict__ W1, const float* __restrict__ W2,
                          const float* __restrict__ Wfc, int N) {
    int idx = blockIdx.x * blockDim.x + threadIdx.x;
    if (idx < 4096) {
        int n = idx & 127, kp = idx >> 7;
        ((__half2*)g_W1h)[idx] =
            __floats2half2_rn(W1[(2 * kp) * 128 + n], W1[(2 * kp + 1) * 128 + n]);
    } else if (idx < 8192) {
        int j = idx - 4096;
        int n = j & 63, kp = j >> 6;
        ((__half2*)g_W2h)[j] =
            __floats2half2_rn(W2[(2 * kp) * 64 + n], W2[(2 * kp + 1) * 64 + n]);
    } else {
        int j = idx - 8192;
        if (j < 27 * 30 * 2048) {
            int kp = j & 31;
            int n  = (j >> 5) & 63;
            int c  = (j >> 11) % 30;
            int nb = j / 61440;            // 30*2048
            int gn = nb * 64 + n;
            int gk = c * 64 + 2 * kp;
            float lo = 0.f, hi = 0.f;
            if (gn < N) {
                lo = Wfc[(long long)gk * N + gn];
                hi = Wfc[(long long)(gk + 1) * N + gn];
            }
            ((__half2*)g_Wt)[j] = __floats2half2_rn(lo, hi);
        }
    }
}

// ---------------- xh = half(dinv * x) ----------------
__global__ void k_scale_x(const float* __restrict__ x, int n) {
    int idx = blockIdx.x * blockDim.x + threadIdx.x;
    if (idx >= n * 32) return;
    int node = idx >> 5;
    float2 v = ((const float2*)x)[idx];
    float di = g_dinv[node];
    ((__half2*)g_xh)[idx] = __floats2half2_rn(v.x * di, v.y * di);
}

// ---------------- gathers (edge loop unrolled x4) ----------------
__global__ void k_gather_in(int n) {
    int w = (blockIdx.x * blockDim.x + threadIdx.x) >> 5;
    int lane = threadIdx.x & 31;
    if (w >= n) return;
    const __half2* src = (const __half2*)g_xh;
    float2 acc = __half22float2(src[w * 32 + lane]);
    int e0 = g_rowptr[w], e1 = g_rowptr[w + 1];
    int e = e0;
    for (; e + 4 <= e1; e += 4) {
        int s0 = g_csr[e], s1 = g_csr[e + 1], s2 = g_csr[e + 2], s3 = g_csr[e + 3];
        float2 v0 = __half22float2(src[s0 * 32 + lane]);
        float2 v1 = __half22float2(src[s1 * 32 + lane]);
        float2 v2 = __half22float2(src[s2 * 32 + lane]);
        float2 v3 = __half22float2(src[s3 * 32 + lane]);
        acc.x += (v0.x + v1.x) + (v2.x + v3.x);
        acc.y += (v0.y + v1.y) + (v2.y + v3.y);
    }
    for (; e < e1; e++) {
        float2 v = __half22float2(src[g_csr[e] * 32 + lane]);
        acc.x += v.x; acc.y += v.y;
    }
    ((__half2*)g_agg1)[w * 32 + lane] = __floats2half2_rn(acc.x, acc.y);
}

__global__ void k_gather_out(const float* __restrict__ b2, int n) {
    int w = (blockIdx.x * blockDim.x + threadIdx.x) >> 5;
    int lane = threadIdx.x & 31;
    if (w >= n) return;
    const __half2* src = (const __half2*)g_g2;
    float2 acc = __half22float2(src[w * 32 + lane]);
    int e0 = g_rowptr[w], e1 = g_rowptr[w + 1];
    int e = e0;
    for (; e + 4 <= e1; e += 4) {
        int s0 = g_csr[e], s1 = g_csr[e + 1], s2 = g_csr[e + 2], s3 = g_csr[e + 3];
        float2 v0 = __half22float2(src[s0 * 32 + lane]);
        float2 v1 = __half22float2(src[s1 * 32 + lane]);
        float2 v2 = __half22float2(src[s2 * 32 + lane]);
        float2 v3 = __half22float2(src[s3 * 32 + lane]);
        acc.x += (v0.x + v1.x) + (v2.x + v3.x);
        acc.y += (v0.y + v1.y) + (v2.y + v3.y);
    }
    for (; e < e1; e++) {
        float2 v = __half22float2(src[g_csr[e] * 32 + lane]);
        acc.x += v.x; acc.y += v.y;
    }
    float di = g_dinv[w];
    float2 bb = *(const float2*)&b2[lane * 2];
    float ox = fmaxf(di * acc.x + bb.x, 0.f);
    float oy = fmaxf(di * acc.y + bb.y, 0.f);
    ((__half2*)g_bufH)[w * 32 + lane] = __floats2half2_rn(ox, oy);
}

// ---------------- GEMM1 fp16 (mma.sync) ----------------
#define G1_LDA 36

__global__ __launch_bounds__(256) void k_gemm1h(const float* __restrict__ b1, int n) {
    __shared__ unsigned As[128 * G1_LDA];
    __shared__ unsigned Bs[32 * 128];
    int tid = threadIdx.x;
    int r0 = blockIdx.x * 128;

    int w = tid >> 5, lane = tid & 31;
    int wm = (w >> 1) * 32, wn = (w & 1) * 64;
    int g = lane >> 2, t = lane & 3;

#pragma unroll
    for (int k = 0; k < 4; k++) {
        int ut = tid + k * 256;
        int row = ut >> 3, q = ut & 7;
        uint4 v = ((const uint4*)(g_agg1 + (long long)(r0 + row) * 64))[q];
        *(uint4*)&As[row * G1_LDA + q * 4] = v;
    }
#pragma unroll
    for (int k = 0; k < 4; k++) {
        int ut = tid + k * 256;
        int kp = ut >> 5, nc = (ut & 31) * 4;
        uint4 v = ((const uint4*)g_W1h)[ut];
        *(uint4*)&Bs[kp * 128 + (nc ^ ((kp & 3) << 3))] = v;
    }
    __syncthreads();

    float c[2][8][4];
#pragma unroll
    for (int i = 0; i < 2; i++)
#pragma unroll
        for (int j = 0; j < 8; j++)
#pragma unroll
            for (int q = 0; q < 4; q++) c[i][j][q] = 0.f;

#pragma unroll
    for (int ks = 0; ks < 4; ks++) {
        unsigned af[2][4];
#pragma unroll
        for (int i = 0; i < 2; i++) {
            int row = wm + 16 * i + g;
            int kp0 = 8 * ks + t;
            af[i][0] = As[row * G1_LDA + kp0];
            af[i][1] = As[(row + 8) * G1_LDA + kp0];
            af[i][2] = As[row * G1_LDA + kp0 + 4];
            af[i][3] = As[(row + 8) * G1_LDA + kp0 + 4];
        }
        unsigned bf[8][2];
#pragma unroll
        for (int j = 0; j < 8; j++) {
            int nn = (wn + 8 * j + g) ^ (t << 3);
            bf[j][0] = Bs[(8 * ks + t) * 128 + nn];
            bf[j][1] = Bs[(8 * ks + 4 + t) * 128 + nn];
        }
#pragma unroll
        for (int i = 0; i < 2; i++)
#pragma unroll
            for (int j = 0; j < 8; j++) {
                asm volatile(
                    "mma.sync.aligned.m16n8k16.row.col.f32.f16.f16.f32 "
                    "{%0,%1,%2,%3}, {%4,%5,%6,%7}, {%8,%9}, {%0,%1,%2,%3};"
                    : "+f"(c[i][j][0]), "+f"(c[i][j][1]),
                      "+f"(c[i][j][2]), "+f"(c[i][j][3])
                    : "r"(af[i][0]), "r"(af[i][1]), "r"(af[i][2]), "r"(af[i][3]),
                      "r"(bf[j][0]), "r"(bf[j][1]));
            }
    }

#pragma unroll
    for (int i = 0; i < 2; i++) {
        int row = wm + 16 * i + g;
#pragma unroll
        for (int j = 0; j < 8; j++) {
            int col = wn + 8 * j + 2 * t;
            float2 bb = *(const float2*)&b1[col];
            int node0 = r0 + row;
            int node1 = node0 + 8;
            float d0 = g_dinv[node0], d1 = g_dinv[node1];
            ((__half2*)g_y1)[(long long)node0 * 64 + col / 2] =
                __floats2half2_rn(fmaxf(d0 * c[i][j][0] + bb.x, 0.f),
                                  fmaxf(d0 * c[i][j][1] + bb.y, 0.f));
            ((__half2*)g_y1)[(long long)node1 * 64 + col / 2] =
                __floats2half2_rn(fmaxf(d1 * c[i][j][2] + bb.x, 0.f),
                                  fmaxf(d1 * c[i][j][3] + bb.y, 0.f));
        }
    }
}

// ---------------- GEMM2 fp16 (mma.sync) ----------------
#define G2_LDA 68

__global__ __launch_bounds__(256) void k_gemm2h(int n) {
    __shared__ unsigned As[64 * G2_LDA];
    __shared__ unsigned Bs[64 * 64];
    int tid = threadIdx.x;
    int r0 = blockIdx.x * 64;

    int w = tid >> 5, lane = tid & 31;
    int wm = (w >> 1) * 16, wn = (w & 1) * 32;
    int g = lane >> 2, t = lane & 3;

#pragma unroll
    for (int k = 0; k < 4; k++) {
        int ut = tid + k * 256;
        int row = ut >> 4, q = ut & 15;
        uint4 v = ((const uint4*)(g_y1 + (long long)(r0 + row) * 128))[q];
        *(uint4*)&As[row * G2_LDA + q * 4] = v;
    }
#pragma unroll
    for (int k = 0; k < 4; k++) {
        int ut = tid + k * 256;
        int kp = ut >> 4, nc = (ut & 15) * 4;
        uint4 v = ((const uint4*)g_W2h)[ut];
        *(uint4*)&Bs[kp * 64 + (nc ^ ((kp & 3) << 3))] = v;
    }
    __syncthreads();

    float c[4][4];
#pragma unroll
    for (int j = 0; j < 4; j++)
#pragma unroll
        for (int q = 0; q < 4; q++) c[j][q] = 0.f;

#pragma unroll
    for (int ks = 0; ks < 8; ks++) {
        unsigned af[4];
        {
            int row = wm + g;
            int kp0 = 8 * ks + t;
            af[0] = As[row * G2_LDA + kp0];
            af[1] = As[(row + 8) * G2_LDA + kp0];
            af[2] = As[row * G2_LDA + kp0 + 4];
            af[3] = As[(row + 8) * G2_LDA + kp0 + 4];
        }
        unsigned bf[4][2];
#pragma unroll
        for (int j = 0; j < 4; j++) {
            int nn = (wn + 8 * j + g) ^ (t << 3);
            bf[j][0] = Bs[(8 * ks + t) * 64 + nn];
            bf[j][1] = Bs[(8 * ks + 4 + t) * 64 + nn];
        }
#pragma unroll
        for (int j = 0; j < 4; j++) {
            asm volatile(
                "mma.sync.aligned.m16n8k16.row.col.f32.f16.f16.f32 "
                "{%0,%1,%2,%3}, {%4,%5,%6,%7}, {%8,%9}, {%0,%1,%2,%3};"
                : "+f"(c[j][0]), "+f"(c[j][1]), "+f"(c[j][2]), "+f"(c[j][3])
                : "r"(af[0]), "r"(af[1]), "r"(af[2]), "r"(af[3]),
                  "r"(bf[j][0]), "r"(bf[j][1]));
        }
    }

    {
        int row = wm + g;
        int node0 = r0 + row, node1 = node0 + 8;
        float d0 = g_dinv[node0], d1 = g_dinv[node1];
#pragma unroll
        for (int j = 0; j < 4; j++) {
            int col = wn + 8 * j + 2 * t;
            ((__half2*)g_g2)[(long long)node0 * 32 + col / 2] =
                __floats2half2_rn(d0 * c[j][0], d0 * c[j][1]);
            ((__half2*)g_g2)[(long long)node1 * 32 + col / 2] =
                __floats2half2_rn(d1 * c[j][2], d1 * c[j][3]);
        }
    }
}

// ---------------- FC fp16 mma.sync (fp32 acc), 2 CTAs/SM ----------------
// Block tile 128m x 64n, 256 thr / 8 warps (4m x 2n of 32x32), BK=64,
// double buffered (register-staged LDG+STS). N=1728=27*64 exactly. 864 CTAs.
// smem: [512:768) bias(64f), stages at 1024.
// stage: A 128x36w (18432B) + B 64x36w (9216B) = 27648B.
#define FC_STG 27648
#define FC_SMEM (1024 + 2 * FC_STG)

__device__ __forceinline__ uint32_t smem_u32(const void* p) {
    uint32_t a;
    asm("{ .reg .u64 t; cvta.to.shared.u64 t, %1; cvt.u32.u64 %0, t; }" : "=r"(a) : "l"(p));
    return a;
}

__global__ __launch_bounds__(256, 2) void k_fc2(const float* __restrict__ bias,
                                                float* __restrict__ out,
                                                int M, int N, int K,
                                                int nchunks) {
    extern __shared__ char sm[];
    uint32_t sb = smem_u32(sm);
    int tid = threadIdx.x, wid = tid >> 5, lane = tid & 31;
    int wm = (wid & 3) * 32, wn = (wid >> 2) * 32;
    int g = lane >> 2, t = lane & 3;
    int lrow = lane & 15, lcolw = (lane >> 4) * 4;
    const __half* A = g_bufH;

    int nb = blockIdx.x % 27;
    int m0 = (blockIdx.x / 27) * 128;
    int n0 = nb * 64;
    const __half2* Bt = (const __half2*)g_Wt + (long long)(nb * 30) * 2048;

    if (tid < 64) *(float*)(sm + 512 + tid * 4) = bias[n0 + tid];

    float c[2][4][4];
#pragma unroll
    for (int i = 0; i < 2; i++)
#pragma unroll
        for (int j = 0; j < 4; j++)
#pragma unroll
            for (int q = 0; q < 4; q++) c[i][j][q] = 0.f;

    // prologue: chunk 0 -> stage 0
#pragma unroll
    for (int i = 0; i < 4; i++) {
        int ut = tid + i * 256;               // 0..1023
        int r = ut >> 3, q = ut & 7;
        uint4 va = ((const uint4*)(A + (long long)(m0 + r) * K))[q];
        *(uint4*)(sm + 1024 + (r * 36 + q * 4) * 4) = va;
    }
#pragma unroll
    for (int i = 0; i < 2; i++) {
        int ut = tid + i * 256;               // 0..511
        int r = ut >> 3, q = ut & 7;
        uint4 vb = ((const uint4*)Bt)[ut];
        *(uint4*)(sm + 1024 + 18432 + (r * 36 + q * 4) * 4) = vb;
    }
    __syncthreads();

    for (int ch = 0; ch < nchunks; ch++) {
        int cur = ch & 1;
        bool hn = (ch + 1) < nchunks;
        uint4 ra[4], rb[2];
        if (hn) {
            int kc = (ch + 1) * 64;
#pragma unroll
            for (int i = 0; i < 4; i++) {
                int ut = tid + i * 256;
                int r = ut >> 3, q = ut & 7;
                ra[i] = ((const uint4*)(A + (long long)(m0 + r) * K + kc))[q];
            }
#pragma unroll
            for (int i = 0; i < 2; i++) {
                int ut = tid + i * 256;
                rb[i] = ((const uint4*)(Bt + (long long)(ch + 1) * 2048))[ut];
            }
        }

        uint32_t sA = sb + 1024 + cur * FC_STG;
        uint32_t sB = sA + 18432;
#pragma unroll
        for (int ks = 0; ks < 4; ks++) {
            int kw = ks * 8 + lcolw;
            unsigned af[2][4], bf[4][2];
#pragma unroll
            for (int i = 0; i < 2; i++) {
                uint32_t ad = sA + (uint32_t)(((wm + 16 * i + lrow) * 36 + kw) * 4);
                asm volatile(
                    "ldmatrix.sync.aligned.m8n8.x4.shared.b16 {%0,%1,%2,%3}, [%4];"
                    : "=r"(af[i][0]), "=r"(af[i][1]), "=r"(af[i][2]), "=r"(af[i][3])
                    : "r"(ad));
            }
#pragma unroll
            for (int jb = 0; jb < 2; jb++) {
                unsigned q0, q1, q2, q3;
                uint32_t bd = sB + (uint32_t)(((wn + 16 * jb + lrow) * 36 + kw) * 4);
                asm volatile(
                    "ldmatrix.sync.aligned.m8n8.x4.shared.b16 {%0,%1,%2,%3}, [%4];"
                    : "=r"(q0), "=r"(q1), "=r"(q2), "=r"(q3)
                    : "r"(bd));
                bf[2 * jb][0] = q0; bf[2 * jb + 1][0] = q1;
                bf[2 * jb][1] = q2; bf[2 * jb + 1][1] = q3;
            }
#pragma unroll
            for (int i = 0; i < 2; i++)
#pragma unroll
                for (int j = 0; j < 4; j++) {
                    asm volatile(
                        "mma.sync.aligned.m16n8k16.row.col.f32.f16.f16.f32 "
                        "{%0,%1,%2,%3}, {%4,%5,%6,%7}, {%8,%9}, {%0,%1,%2,%3};"
                        : "+f"(c[i][j][0]), "+f"(c[i][j][1]),
                          "+f"(c[i][j][2]), "+f"(c[i][j][3])
                        : "r"(af[i][0]), "r"(af[i][1]), "r"(af[i][2]), "r"(af[i][3]),
                          "r"(bf[j][0]), "r"(bf[j][1]));
                }
        }

        if (hn) {
            char* dA = sm + 1024 + ((ch + 1) & 1) * FC_STG;
#pragma unroll
            for (int i = 0; i < 4; i++) {
                int ut = tid + i * 256;
                int r = ut >> 3, q = ut & 7;
                *(uint4*)(dA + (r * 36 + q * 4) * 4) = ra[i];
            }
#pragma unroll
            for (int i = 0; i < 2; i++) {
                int ut = tid + i * 256;
                int r = ut >> 3, q = ut & 7;
                *(uint4*)(dA + 18432 + (r * 36 + q * 4) * 4) = rb[i];
            }
        }
        __syncthreads();
    }

    // epilogue
    const float* bs = (const float*)(sm + 512);
#pragma unroll
    for (int i = 0; i < 2; i++) {
        int row = m0 + wm + 16 * i + g;
#pragma unroll
        for (int j = 0; j < 4; j++) {
            int lb = wn + 8 * j + 2 * t;
            int cb = n0 + lb;
            float2 bb = make_float2(bs[lb], bs[lb + 1]);
            float2 o0 = make_float2(c[i][j][0] + bb.x, c[i][j][1] + bb.y);
            float2 o1 = make_float2(c[i][j][2] + bb.x, c[i][j][3] + bb.y);
            *(float2*)&out[(long long)row * N + cb] = o0;
            *(float2*)&out[(long long)(row + 8) * N + cb] = o1;
        }
    }
}

// ---------------- launch ----------------
extern "C" void kernel_launch(void* const* d_in, const int* in_sizes, int n_in,
                              void* d_out, int out_size) {
    const float* x   = (const float*)d_in[0];
    const int*   ei  = (const int*)d_in[1];
    const float* W1  = (const float*)d_in[2];
    const float* b1  = (const float*)d_in[3];
    const float* W2  = (const float*)d_in[4];
    const float* b2  = (const float*)d_in[5];
    const float* Wfc = (const float*)d_in[6];
    const float* bfc = (const float*)d_in[7];
    float* out = (float*)d_out;

    int n = in_sizes[0] / 64;     // 122880
    int E = in_sizes[1] / 2;      // 983040
    int M = out_size / 1728;      // 4096
    int Nfc = 1728, Kfc = 1920;
    int ntiles = 27 * (M / 128);  // 864

    static int fc_attr_set = 0;
    if (!fc_attr_set) {
        cudaFuncSetAttribute(k_fc2, cudaFuncAttributeMaxDynamicSharedMemorySize, FC_SMEM);
        fc_attr_set = 1;
    }

    // graph structure
    k_zero_detect<<<(n + 255) / 256, 256>>>(ei, n);
    k_count<<<(E + 255) / 256, 256>>>(ei, E, n);
    int nb = (n + 1023) / 1024;
    k_scan1<<<nb, 1024>>>(n);
    k_scan2<<<1, 1024>>>(nb);
    k_scan3<<<nb, 1024>>>(n, E);
    k_fill<<<(E + 255) / 256, 256>>>(ei, E, n);

    // weights (single kernel)
    int cvt_tot = 8192 + 27 * 30 * 2048;
    k_cvt_all<<<(cvt_tot + 255) / 256, 256>>>(W1, W2, Wfc, Nfc);

    // node pipeline
    k_scale_x<<<(n * 32 + 255) / 256, 256>>>(x, n);
    k_gather_in<<<(n * 32 + 255) / 256, 256>>>(n);
    k_gemm1h<<<n / 128, 256>>>(b1, n);
    k_gemm2h<<<n / 64, 256>>>(n);
    k_gather_out<<<(n * 32 + 255) / 256, 256>>>(b2, n);

    // FC head: 864 CTAs, 2 per SM
    k_fc2<<<ntiles, 256, FC_SMEM>>>(bfc, out, M, Nfc, Kfc, 30);
}

// round 16
// speedup vs baseline: 1.0837x; 1.0325x over previous
#include <cuda_runtime.h>
#include <cuda_fp16.h>
#include <cstdint>

// ---------------- static scratch (no allocations allowed) ----------------
#define NMAX 122880
#define EMAX 983040

__device__ float g_dinv[NMAX];
__device__ int   g_deg[NMAX];
__device__ int   g_rowptr[NMAX + 1];
__device__ int   g_cursor[NMAX];
__device__ int   g_csr[EMAX];
__device__ int   g_bsum[256];
__device__ int   g_is64;

__device__ __half g_xh[NMAX * 64];
__device__ __half g_agg1[NMAX * 64];
__device__ __half g_y1[NMAX * 128];
__device__ __half g_g2[NMAX * 64];
__device__ __half g_bufH[NMAX * 64];            // FC A operand [4096][1920]
__device__ __half g_W1h[32 * 128 * 2];
__device__ __half g_W2h[64 * 64 * 2];
// Wfc^T for FC: [27 nblk][30 kchunk][64 n][32 kp] half2 linear
__device__ __half g_Wt[14 * 30 * 8192];         // (reuse; 27*30*4096 = 3.32M <= 3.44M)

// ---------------- zero degrees + dtype detection (merged) ----------------
__global__ void k_zero_detect(const int* __restrict__ w, int n) {
    int i = blockIdx.x * blockDim.x + threadIdx.x;
    if (i < n) g_deg[i] = 0;
    if (i == 0) g_is64 = 1;
    if (i < 4096 && (i & 1) && w[i] != 0) g_is64 = 0;
}

__device__ __forceinline__ int load_idx(const int* w, long long pos) {
    return g_is64 ? w[2 * pos] : w[(int)pos];
}

// ---------------- degree count + ALL weight conversions (merged) ----------
#define CVT_W1  4096
#define CVT_W2  4096
#define CVT_WT  (27 * 30 * 2048)
#define CVT_TOT (CVT_W1 + CVT_W2 + CVT_WT)

__global__ void k_count_cvt(const int* __restrict__ w, int E, int n,
                            const float* __restrict__ W1,
                            const float* __restrict__ W2,
                            const float* __restrict__ Wfc, int N) {
    int gid = blockIdx.x * blockDim.x + threadIdx.x;
    if (gid < E) {
        int d = load_idx(w, (long long)E + gid);
        d = min(max(d, 0), n - 1);
        atomicAdd(&g_deg[d], 1);
        return;
    }
    int idx = gid - E;
    if (idx < CVT_W1) {
        int nn = idx & 127, kp = idx >> 7;
        ((__half2*)g_W1h)[idx] =
            __floats2half2_rn(W1[(2 * kp) * 128 + nn], W1[(2 * kp + 1) * 128 + nn]);
    } else if (idx < CVT_W1 + CVT_W2) {
        int j = idx - CVT_W1;
        int nn = j & 63, kp = j >> 6;
        ((__half2*)g_W2h)[j] =
            __floats2half2_rn(W2[(2 * kp) * 64 + nn], W2[(2 * kp + 1) * 64 + nn]);
    } else if (idx < CVT_TOT) {
        int j = idx - CVT_W1 - CVT_W2;
        int kp = j & 31;
        int nn = (j >> 5) & 63;
        int c  = (j >> 11) % 30;
        int nb = j / 61440;            // 30*2048
        int gn = nb * 64 + nn;
        int gk = c * 64 + 2 * kp;
        float lo = 0.f, hi = 0.f;
        if (gn < N) {
            lo = Wfc[(long long)gk * N + gn];
            hi = Wfc[(long long)(gk + 1) * N + gn];
        }
        ((__half2*)g_Wt)[j] = __floats2half2_rn(lo, hi);
    }
}

// ---------------- scan1: per-block inclusive scan + dinv ----------------
__global__ void k_scan1(int n) {
    __shared__ int sh[1024];
    int gid = blockIdx.x * 1024 + threadIdx.x;
    int v = (gid < n) ? g_deg[gid] : 0;
    sh[threadIdx.x] = v;
    __syncthreads();
    for (int off = 1; off < 1024; off <<= 1) {
        int t = (threadIdx.x >= off) ? sh[threadIdx.x - off] : 0;
        __syncthreads();
        sh[threadIdx.x] += t;
        __syncthreads();
    }
    if (gid < n) {
        g_rowptr[gid] = sh[threadIdx.x] - v;
        g_dinv[gid] = rsqrtf((float)(v + 1));
    }
    if (threadIdx.x == 1023) g_bsum[blockIdx.x] = sh[1023];
}

// ---------------- scan3: inline block-sum prefix (replaces scan2+scan3) ----
__global__ void k_scan3(int n, int E) {
    __shared__ int base_sh;
    int tid = threadIdx.x;
    if (tid < 32) {
        int s = 0;
        for (int i = tid; i < blockIdx.x; i += 32) s += g_bsum[i];
#pragma unroll
        for (int o = 16; o > 0; o >>= 1) s += __shfl_xor_sync(0xffffffffu, s, o);
        if (tid == 0) base_sh = s;
    }
    __syncthreads();
    int base = base_sh;
    int gid = blockIdx.x * 1024 + tid;
    if (gid < n) {
        int r = g_rowptr[gid] + base;
        g_rowptr[gid] = r;
        g_cursor[gid] = r;
    }
    if (gid == 0) g_rowptr[n] = E;
}

// ---------------- CSR fill + x scaling (merged) ----------------
__global__ void k_fill_scale(const int* __restrict__ w, int E, int n,
                             const float* __restrict__ x) {
    int gid = blockIdx.x * blockDim.x + threadIdx.x;
    if (gid < E) {
        int d = load_idx(w, (long long)E + gid);
        int s = load_idx(w, gid);
        d = min(max(d, 0), n - 1);
        s = min(max(s, 0), n - 1);
        int slot = atomicAdd(&g_cursor[d], 1);
        g_csr[min(slot, EMAX - 1)] = s;
        return;
    }
    int idx = gid - E;
    if (idx < n * 32) {
        int node = idx >> 5;
        float2 v = ((const float2*)x)[idx];
        float di = g_dinv[node];
        ((__half2*)g_xh)[idx] = __floats2half2_rn(v.x * di, v.y * di);
    }
}

// ---------------- gathers (edge loop unrolled x4) ----------------
__global__ void k_gather_in(int n) {
    int w = (blockIdx.x * blockDim.x + threadIdx.x) >> 5;
    int lane = threadIdx.x & 31;
    if (w >= n) return;
    const __half2* src = (const __half2*)g_xh;
    float2 acc = __half22float2(src[w * 32 + lane]);
    int e0 = g_rowptr[w], e1 = g_rowptr[w + 1];
    int e = e0;
    for (; e + 4 <= e1; e += 4) {
        int s0 = g_csr[e], s1 = g_csr[e + 1], s2 = g_csr[e + 2], s3 = g_csr[e + 3];
        float2 v0 = __half22float2(src[s0 * 32 + lane]);
        float2 v1 = __half22float2(src[s1 * 32 + lane]);
        float2 v2 = __half22float2(src[s2 * 32 + lane]);
        float2 v3 = __half22float2(src[s3 * 32 + lane]);
        acc.x += (v0.x + v1.x) + (v2.x + v3.x);
        acc.y += (v0.y + v1.y) + (v2.y + v3.y);
    }
    for (; e < e1; e++) {
        float2 v = __half22float2(src[g_csr[e] * 32 + lane]);
        acc.x += v.x; acc.y += v.y;
    }
    ((__half2*)g_agg1)[w * 32 + lane] = __floats2half2_rn(acc.x, acc.y);
}

__global__ void k_gather_out(const float* __restrict__ b2, int n) {
    int w = (blockIdx.x * blockDim.x + threadIdx.x) >> 5;
    int lane = threadIdx.x & 31;
    if (w >= n) return;
    const __half2* src = (const __half2*)g_g2;
    float2 acc = __half22float2(src[w * 32 + lane]);
    int e0 = g_rowptr[w], e1 = g_rowptr[w + 1];
    int e = e0;
    for (; e + 4 <= e1; e += 4) {
        int s0 = g_csr[e], s1 = g_csr[e + 1], s2 = g_csr[e + 2], s3 = g_csr[e + 3];
        float2 v0 = __half22float2(src[s0 * 32 + lane]);
        float2 v1 = __half22float2(src[s1 * 32 + lane]);
        float2 v2 = __half22float2(src[s2 * 32 + lane]);
        float2 v3 = __half22float2(src[s3 * 32 + lane]);
        acc.x += (v0.x + v1.x) + (v2.x + v3.x);
        acc.y += (v0.y + v1.y) + (v2.y + v3.y);
    }
    for (; e < e1; e++) {
        float2 v = __half22float2(src[g_csr[e] * 32 + lane]);
        acc.x += v.x; acc.y += v.y;
    }
    float di = g_dinv[w];
    float2 bb = *(const float2*)&b2[lane * 2];
    float ox = fmaxf(di * acc.x + bb.x, 0.f);
    float oy = fmaxf(di * acc.y + bb.y, 0.f);
    ((__half2*)g_bufH)[w * 32 + lane] = __floats2half2_rn(ox, oy);
}

// ---------------- GEMM1 fp16 (mma.sync) ----------------
#define G1_LDA 36

__global__ __launch_bounds__(256) void k_gemm1h(const float* __restrict__ b1, int n) {
    __shared__ unsigned As[128 * G1_LDA];
    __shared__ unsigned Bs[32 * 128];
    int tid = threadIdx.x;
    int r0 = blockIdx.x * 128;

    int w = tid >> 5, lane = tid & 31;
    int wm = (w >> 1) * 32, wn = (w & 1) * 64;
    int g = lane >> 2, t = lane & 3;

#pragma unroll
    for (int k = 0; k < 4; k++) {
        int ut = tid + k * 256;
        int row = ut >> 3, q = ut & 7;
        uint4 v = ((const uint4*)(g_agg1 + (long long)(r0 + row) * 64))[q];
        *(uint4*)&As[row * G1_LDA + q * 4] = v;
    }
#pragma unroll
    for (int k = 0; k < 4; k++) {
        int ut = tid + k * 256;
        int kp = ut >> 5, nc = (ut & 31) * 4;
        uint4 v = ((const uint4*)g_W1h)[ut];
        *(uint4*)&Bs[kp * 128 + (nc ^ ((kp & 3) << 3))] = v;
    }
    __syncthreads();

    float c[2][8][4];
#pragma unroll
    for (int i = 0; i < 2; i++)
#pragma unroll
        for (int j = 0; j < 8; j++)
#pragma unroll
            for (int q = 0; q < 4; q++) c[i][j][q] = 0.f;

#pragma unroll
    for (int ks = 0; ks < 4; ks++) {
        unsigned af[2][4];
#pragma unroll
        for (int i = 0; i < 2; i++) {
            int row = wm + 16 * i + g;
            int kp0 = 8 * ks + t;
            af[i][0] = As[row * G1_LDA + kp0];
            af[i][1] = As[(row + 8) * G1_LDA + kp0];
            af[i][2] = As[row * G1_LDA + kp0 + 4];
            af[i][3] = As[(row + 8) * G1_LDA + kp0 + 4];
        }
        unsigned bf[8][2];
#pragma unroll
        for (int j = 0; j < 8; j++) {
            int nn = (wn + 8 * j + g) ^ (t << 3);
            bf[j][0] = Bs[(8 * ks + t) * 128 + nn];
            bf[j][1] = Bs[(8 * ks + 4 + t) * 128 + nn];
        }
#pragma unroll
        for (int i = 0; i < 2; i++)
#pragma unroll
            for (int j = 0; j < 8; j++) {
                asm volatile(
                    "mma.sync.aligned.m16n8k16.row.col.f32.f16.f16.f32 "
                    "{%0,%1,%2,%3}, {%4,%5,%6,%7}, {%8,%9}, {%0,%1,%2,%3};"
                    : "+f"(c[i][j][0]), "+f"(c[i][j][1]),
                      "+f"(c[i][j][2]), "+f"(c[i][j][3])
                    : "r"(af[i][0]), "r"(af[i][1]), "r"(af[i][2]), "r"(af[i][3]),
                      "r"(bf[j][0]), "r"(bf[j][1]));
            }
    }

#pragma unroll
    for (int i = 0; i < 2; i++) {
        int row = wm + 16 * i + g;
#pragma unroll
        for (int j = 0; j < 8; j++) {
            int col = wn + 8 * j + 2 * t;
            float2 bb = *(const float2*)&b1[col];
            int node0 = r0 + row;
            int node1 = node0 + 8;
            float d0 = g_dinv[node0], d1 = g_dinv[node1];
            ((__half2*)g_y1)[(long long)node0 * 64 + col / 2] =
                __floats2half2_rn(fmaxf(d0 * c[i][j][0] + bb.x, 0.f),
                                  fmaxf(d0 * c[i][j][1] + bb.y, 0.f));
            ((__half2*)g_y1)[(long long)node1 * 64 + col / 2] =
                __floats2half2_rn(fmaxf(d1 * c[i][j][2] + bb.x, 0.f),
                                  fmaxf(d1 * c[i][j][3] + bb.y, 0.f));
        }
    }
}

// ---------------- GEMM2 fp16 (mma.sync) ----------------
#define G2_LDA 68

__global__ __launch_bounds__(256) void k_gemm2h(int n) {
    __shared__ unsigned As[64 * G2_LDA];
    __shared__ unsigned Bs[64 * 64];
    int tid = threadIdx.x;
    int r0 = blockIdx.x * 64;

    int w = tid >> 5, lane = tid & 31;
    int wm = (w >> 1) * 16, wn = (w & 1) * 32;
    int g = lane >> 2, t = lane & 3;

#pragma unroll
    for (int k = 0; k < 4; k++) {
        int ut = tid + k * 256;
        int row = ut >> 4, q = ut & 15;
        uint4 v = ((const uint4*)(g_y1 + (long long)(r0 + row) * 128))[q];
        *(uint4*)&As[row * G2_LDA + q * 4] = v;
    }
#pragma unroll
    for (int k = 0; k < 4; k++) {
        int ut = tid + k * 256;
        int kp = ut >> 4, nc = (ut & 15) * 4;
        uint4 v = ((const uint4*)g_W2h)[ut];
        *(uint4*)&Bs[kp * 64 + (nc ^ ((kp & 3) << 3))] = v;
    }
    __syncthreads();

    float c[4][4];
#pragma unroll
    for (int j = 0; j < 4; j++)
#pragma unroll
        for (int q = 0; q < 4; q++) c[j][q] = 0.f;

#pragma unroll
    for (int ks = 0; ks < 8; ks++) {
        unsigned af[4];
        {
            int row = wm + g;
            int kp0 = 8 * ks + t;
            af[0] = As[row * G2_LDA + kp0];
            af[1] = As[(row + 8) * G2_LDA + kp0];
            af[2] = As[row * G2_LDA + kp0 + 4];
            af[3] = As[(row + 8) * G2_LDA + kp0 + 4];
        }
        unsigned bf[4][2];
#pragma unroll
        for (int j = 0; j < 4; j++) {
            int nn = (wn + 8 * j + g) ^ (t << 3);
            bf[j][0] = Bs[(8 * ks + t) * 64 + nn];
            bf[j][1] = Bs[(8 * ks + 4 + t) * 64 + nn];
        }
#pragma unroll
        for (int j = 0; j < 4; j++) {
            asm volatile(
                "mma.sync.aligned.m16n8k16.row.col.f32.f16.f16.f32 "
                "{%0,%1,%2,%3}, {%4,%5,%6,%7}, {%8,%9}, {%0,%1,%2,%3};"
                : "+f"(c[j][0]), "+f"(c[j][1]), "+f"(c[j][2]), "+f"(c[j][3])
                : "r"(af[0]), "r"(af[1]), "r"(af[2]), "r"(af[3]),
                  "r"(bf[j][0]), "r"(bf[j][1]));
        }
    }

    {
        int row = wm + g;
        int node0 = r0 + row, node1 = node0 + 8;
        float d0 = g_dinv[node0], d1 = g_dinv[node1];
#pragma unroll
        for (int j = 0; j < 4; j++) {
            int col = wn + 8 * j + 2 * t;
            ((__half2*)g_g2)[(long long)node0 * 32 + col / 2] =
                __floats2half2_rn(d0 * c[j][0], d0 * c[j][1]);
            ((__half2*)g_g2)[(long long)node1 * 32 + col / 2] =
                __floats2half2_rn(d1 * c[j][2], d1 * c[j][3]);
        }
    }
}

// ---------------- FC fp16 mma.sync (fp32 acc), 2 CTAs/SM ----------------
// Block tile 128m x 64n, 256 thr / 8 warps (4m x 2n of 32x32), BK=64,
// double buffered (register-staged LDG+STS). N=1728=27*64 exactly. 864 CTAs.
#define FC_STG 27648
#define FC_SMEM (1024 + 2 * FC_STG)

__device__ __forceinline__ uint32_t smem_u32(const void* p) {
    uint32_t a;
    asm("{ .reg .u64 t; cvta.to.shared.u64 t, %1; cvt.u32.u64 %0, t; }" : "=r"(a) : "l"(p));
    return a;
}

__global__ __launch_bounds__(256, 2) void k_fc2(const float* __restrict__ bias,
                                                float* __restrict__ out,
                                                int M, int N, int K,
                                                int nchunks) {
    extern __shared__ char sm[];
    uint32_t sb = smem_u32(sm);
    int tid = threadIdx.x, wid = tid >> 5, lane = tid & 31;
    int wm = (wid & 3) * 32, wn = (wid >> 2) * 32;
    int g = lane >> 2, t = lane & 3;
    int lrow = lane & 15, lcolw = (lane >> 4) * 4;
    const __half* A = g_bufH;

    int nb = blockIdx.x % 27;
    int m0 = (blockIdx.x / 27) * 128;
    int n0 = nb * 64;
    const __half2* Bt = (const __half2*)g_Wt + (long long)(nb * 30) * 2048;

    if (tid < 64) *(float*)(sm + 512 + tid * 4) = bias[n0 + tid];

    float c[2][4][4];
#pragma unroll
    for (int i = 0; i < 2; i++)
#pragma unroll
        for (int j = 0; j < 4; j++)
#pragma unroll
            for (int q = 0; q < 4; q++) c[i][j][q] = 0.f;

    // prologue: chunk 0 -> stage 0
#pragma unroll
    for (int i = 0; i < 4; i++) {
        int ut = tid + i * 256;               // 0..1023
        int r = ut >> 3, q = ut & 7;
        uint4 va = ((const uint4*)(A + (long long)(m0 + r) * K))[q];
        *(uint4*)(sm + 1024 + (r * 36 + q * 4) * 4) = va;
    }
#pragma unroll
    for (int i = 0; i < 2; i++) {
        int ut = tid + i * 256;               // 0..511
        int r = ut >> 3, q = ut & 7;
        uint4 vb = ((const uint4*)Bt)[ut];
        *(uint4*)(sm + 1024 + 18432 + (r * 36 + q * 4) * 4) = vb;
    }
    __syncthreads();

    for (int ch = 0; ch < nchunks; ch++) {
        int cur = ch & 1;
        bool hn = (ch + 1) < nchunks;
        uint4 ra[4], rb[2];
        if (hn) {
            int kc = (ch + 1) * 64;
#pragma unroll
            for (int i = 0; i < 4; i++) {
                int ut = tid + i * 256;
                int r = ut >> 3, q = ut & 7;
                ra[i] = ((const uint4*)(A + (long long)(m0 + r) * K + kc))[q];
            }
#pragma unroll
            for (int i = 0; i < 2; i++) {
                int ut = tid + i * 256;
                rb[i] = ((const uint4*)(Bt + (long long)(ch + 1) * 2048))[ut];
            }
        }

        uint32_t sA = sb + 1024 + cur * FC_STG;
        uint32_t sB = sA + 18432;
#pragma unroll
        for (int ks = 0; ks < 4; ks++) {
            int kw = ks * 8 + lcolw;
            unsigned af[2][4], bf[4][2];
#pragma unroll
            for (int i = 0; i < 2; i++) {
                uint32_t ad = sA + (uint32_t)(((wm + 16 * i + lrow) * 36 + kw) * 4);
                asm volatile(
                    "ldmatrix.sync.aligned.m8n8.x4.shared.b16 {%0,%1,%2,%3}, [%4];"
                    : "=r"(af[i][0]), "=r"(af[i][1]), "=r"(af[i][2]), "=r"(af[i][3])
                    : "r"(ad));
            }
#pragma unroll
            for (int jb = 0; jb < 2; jb++) {
                unsigned q0, q1, q2, q3;
                uint32_t bd = sB + (uint32_t)(((wn + 16 * jb + lrow) * 36 + kw) * 4);
                asm volatile(
                    "ldmatrix.sync.aligned.m8n8.x4.shared.b16 {%0,%1,%2,%3}, [%4];"
                    : "=r"(q0), "=r"(q1), "=r"(q2), "=r"(q3)
                    : "r"(bd));
                bf[2 * jb][0] = q0; bf[2 * jb + 1][0] = q1;
                bf[2 * jb][1] = q2; bf[2 * jb + 1][1] = q3;
            }
#pragma unroll
            for (int i = 0; i < 2; i++)
#pragma unroll
                for (int j = 0; j < 4; j++) {
                    asm volatile(
                        "mma.sync.aligned.m16n8k16.row.col.f32.f16.f16.f32 "
                        "{%0,%1,%2,%3}, {%4,%5,%6,%7}, {%8,%9}, {%0,%1,%2,%3};"
                        : "+f"(c[i][j][0]), "+f"(c[i][j][1]),
                          "+f"(c[i][j][2]), "+f"(c[i][j][3])
                        : "r"(af[i][0]), "r"(af[i][1]), "r"(af[i][2]), "r"(af[i][3]),
                          "r"(bf[j][0]), "r"(bf[j][1]));
                }
        }

        if (hn) {
            char* dA = sm + 1024 + ((ch + 1) & 1) * FC_STG;
#pragma unroll
            for (int i = 0; i < 4; i++) {
                int ut = tid + i * 256;
                int r = ut >> 3, q = ut & 7;
                *(uint4*)(dA + (r * 36 + q * 4) * 4) = ra[i];
            }
#pragma unroll
            for (int i = 0; i < 2; i++) {
                int ut = tid + i * 256;
                int r = ut >> 3, q = ut & 7;
                *(uint4*)(dA + 18432 + (r * 36 + q * 4) * 4) = rb[i];
            }
        }
        __syncthreads();
    }

    // epilogue
    const float* bs = (const float*)(sm + 512);
#pragma unroll
    for (int i = 0; i < 2; i++) {
        int row = m0 + wm + 16 * i + g;
#pragma unroll
        for (int j = 0; j < 4; j++) {
            int lb = wn + 8 * j + 2 * t;
            int cb = n0 + lb;
            float2 bb = make_float2(bs[lb], bs[lb + 1]);
            float2 o0 = make_float2(c[i][j][0] + bb.x, c[i][j][1] + bb.y);
            float2 o1 = make_float2(c[i][j][2] + bb.x, c[i][j][3] + bb.y);
            *(float2*)&out[(long long)row * N + cb] = o0;
            *(float2*)&out[(long long)(row + 8) * N + cb] = o1;
        }
    }
}

// ---------------- launch ----------------
extern "C" void kernel_launch(void* const* d_in, const int* in_sizes, int n_in,
                              void* d_out, int out_size) {
    const float* x   = (const float*)d_in[0];
    const int*   ei  = (const int*)d_in[1];
    const float* W1  = (const float*)d_in[2];
    const float* b1  = (const float*)d_in[3];
    const float* W2  = (const float*)d_in[4];
    const float* b2  = (const float*)d_in[5];
    const float* Wfc = (const float*)d_in[6];
    const float* bfc = (const float*)d_in[7];
    float* out = (float*)d_out;

    int n = in_sizes[0] / 64;     // 122880
    int E = in_sizes[1] / 2;      // 983040
    int M = out_size / 1728;      // 4096
    int Nfc = 1728, Kfc = 1920;
    int ntiles = 27 * (M / 128);  // 864

    static int fc_attr_set = 0;
    if (!fc_attr_set) {
        cudaFuncSetAttribute(k_fc2, cudaFuncAttributeMaxDynamicSharedMemorySize, FC_SMEM);
        fc_attr_set = 1;
    }

    // 1) zero degrees + dtype detect
    k_zero_detect<<<(n + 255) / 256, 256>>>(ei, n);
    // 2) degree count + all weight conversions
    int cc_tot = E + CVT_TOT;
    k_count_cvt<<<(cc_tot + 255) / 256, 256>>>(ei, E, n, W1, W2, Wfc, Nfc);
    // 3) per-block scan + dinv
    int nb = (n + 1023) / 1024;
    k_scan1<<<nb, 1024>>>(n);
    // 4) global offsets (inline block-sum prefix)
    k_scan3<<<nb, 1024>>>(n, E);
    // 5) CSR fill + x scaling
    int fs_tot = E + n * 32;
    k_fill_scale<<<(fs_tot + 255) / 256, 256>>>(ei, E, n, x);

    // node pipeline
    k_gather_in<<<(n * 32 + 255) / 256, 256>>>(n);
    k_gemm1h<<<n / 128, 256>>>(b1, n);
    k_gemm2h<<<n / 64, 256>>>(n);
    k_gather_out<<<(n * 32 + 255) / 256, 256>>>(b2, n);

    // FC head: 864 CTAs, 2 per SM
    k_fc2<<<ntiles, 256, FC_SMEM>>>(bfc, out, M, Nfc, Kfc, 30);
}